// round 4
// baseline (speedup 1.0000x reference)
#include <cuda_runtime.h>
#include <cstdint>
#include <math.h>

// SoftmaxSetAttention, GB300 (plain sm_103 target -> legacy mma.sync tf32).
// Warp-specialized ping-pong:
//   warps 0-7  (A): S = Q K^T (tf32 mma), fixed-max base-2 softmax, P -> smem
//   warps 8-15 (B): O += P V  (tf32 mma), P fragments read from smem
// A(i) overlaps B(i-1). K: 2 stages (A-owned cp.async), V: 3 stages (B-owned),
// P: single buffer, per-thread-contiguous 144B chunks (conflict-free v4).
// Numerics = round 2: K/V raw fp32 bits into tf32 mma (RZ truncation) with
// bias compensation in scale (K) and epilogue (V); Q and P via cvt.rna.

#define BATCH 2
#define HEADS 16
#define LQ 2048
#define LK 2048
#define DD 128
#define BC 64
#define NKT 32
#define NTHREADS 512
#define PADF 132

#define KSTG_B   (BC * PADF * 4)            // 33792 bytes per K/V stage
#define K_OFF    0u                         // 2 stages (also Q staging area)
#define V_OFF    (2u * KSTG_B)              // 3 stages
#define P_OFF    (V_OFF + 3u * KSTG_B)      // 256 chunks x 144 B
#define PCH      144u
#define LM_OFF   (P_OFF + 256u * PCH)       // float lm[2][64]
#define LINV_OFF (LM_OFF + 512u)            // float linv[128]
#define SMEM_BYTES (LINV_OFF + 512u)

__device__ __forceinline__ uint32_t f2tf(float x) {
    uint32_t r; asm("cvt.rna.tf32.f32 %0, %1;" : "=r"(r) : "f"(x)); return r;
}
__device__ __forceinline__ float ex2f(float x) {
    float r; asm("ex2.approx.ftz.f32 %0, %1;" : "=f"(r) : "f"(x)); return r;
}
__device__ __forceinline__ void mma8(float c[4], const uint32_t a[4], uint32_t b0, uint32_t b1) {
    asm volatile(
        "mma.sync.aligned.m16n8k8.row.col.f32.tf32.tf32.f32 "
        "{%0,%1,%2,%3}, {%4,%5,%6,%7}, {%8,%9}, {%0,%1,%2,%3};"
        : "+f"(c[0]), "+f"(c[1]), "+f"(c[2]), "+f"(c[3])
        : "r"(a[0]), "r"(a[1]), "r"(a[2]), "r"(a[3]), "r"(b0), "r"(b1));
}
__device__ __forceinline__ void cp16(uint32_t dst, const void* src) {
    asm volatile("cp.async.cg.shared.global [%0], [%1], 16;" :: "r"(dst), "l"(src));
}
#define CP_COMMIT() asm volatile("cp.async.commit_group;" ::: "memory")
#define CP_WAIT(n)  asm volatile("cp.async.wait_group %0;" :: "n"(n) : "memory")
#define BAR(id)     asm volatile("bar.sync %0, %1;" :: "r"(id), "r"(NTHREADS) : "memory")
#define STS128(a, v0, v1, v2, v3) \
    asm volatile("st.shared.v4.b32 [%0], {%1, %2, %3, %4};" \
                 :: "r"(a), "r"(v0), "r"(v1), "r"(v2), "r"(v3) : "memory")
#define LDS128(v0, v1, v2, v3, a) \
    asm volatile("ld.shared.v4.b32 {%0, %1, %2, %3}, [%4];" \
                 : "=r"(v0), "=r"(v1), "=r"(v2), "=r"(v3) : "r"(a))

__global__ void __launch_bounds__(NTHREADS, 1)
ssa_ws_kernel(const float* __restrict__ Q, const float* __restrict__ K,
              const float* __restrict__ V, const int* __restrict__ MULT,
              float* __restrict__ O)
{
    extern __shared__ float smem[];
    const uint32_t sb = (uint32_t)__cvta_generic_to_shared(smem);

    const int tid  = threadIdx.x;
    const int lane = tid & 31;
    const int g    = lane >> 2;
    const int tq   = lane & 3;
    const int bh   = blockIdx.y;
    const int qt   = blockIdx.x;
    const int b    = bh / HEADS;

    const float* Qp = Q + ((size_t)bh * LQ + (size_t)qt * 128) * DD;
    const float* Kp = K + (size_t)bh * LK * DD;
    const float* Vp = V + (size_t)bh * LK * DD;
    const int*   Mp = MULT + (size_t)b * LK;
    float*       Op = O + ((size_t)bh * LQ + (size_t)qt * 128) * DD;

    const float scale2 = (1.4426950408889634f / 11.313708498984760f) * (1.0f + 0.000244140625f);
    const float FIXMAX = 16.0f;
    const float comp   = 1.0f + 0.000244140625f;

    // ---- uniform prologue: stage Q (PAD-132 layout) into K region ----
    #pragma unroll
    for (int i = 0; i < 8; i++) {
        int idx = tid + i * NTHREADS;          // 0..4095 float4 chunks
        int row = idx >> 5, dc = idx & 31;
        cp16(sb + (uint32_t)(row * PADF + dc * 4) * 4u, Qp + (size_t)row * DD + dc * 4);
    }
    CP_COMMIT();
    CP_WAIT(0);
    __syncthreads();

    if (tid < 256) {
        // ===================== GROUP A: S + softmax =====================
        const int wg = tid >> 5;               // 0..7
        uint32_t qa[16][4];
        {
            const int r0 = wg * 16 + g;
            const float* q0 = smem + r0 * PADF;
            const float* q1 = smem + (r0 + 8) * PADF;
            #pragma unroll
            for (int ks = 0; ks < 16; ks++) {
                qa[ks][0] = f2tf(q0[ks * 8 + tq]);
                qa[ks][1] = f2tf(q1[ks * 8 + tq]);
                qa[ks][2] = f2tf(q0[ks * 8 + tq + 4]);
                qa[ks][3] = f2tf(q1[ks * 8 + tq + 4]);
            }
        }
        __syncthreads();                        // Q consumed; K stages may be written

        float mv = 1.0f;
        if (tid < BC) mv = (float)Mp[tid];

        // K(0) into stage 0 (A threads: 2048 chunks / 256 = 8 each)
        {
            const float* kg = Kp;
            #pragma unroll
            for (int i = 0; i < 8; i++) {
                int idx = tid + i * 256;
                int row = idx >> 5, dc = idx & 31;
                cp16(sb + K_OFF + (uint32_t)(row * PADF + dc * 4) * 4u,
                     kg + (size_t)row * DD + dc * 4);
            }
        }
        CP_COMMIT();

        float l_r[2] = {0.f, 0.f};
        float sc[8][4];
        const uint32_t pbase = sb + P_OFF + (uint32_t)tid * PCH;

        #pragma unroll 1
        for (int i = 0; i <= NKT; i++) {
            if (i + 1 < NKT) {                  // issue K(i+1)
                const uint32_t kd = sb + K_OFF + (uint32_t)((i + 1) & 1) * KSTG_B;
                const float* kg = Kp + (size_t)(i + 1) * BC * DD;
                #pragma unroll
                for (int j = 0; j < 8; j++) {
                    int idx = tid + j * 256;
                    int row = idx >> 5, dc = idx & 31;
                    cp16(kd + (uint32_t)(row * PADF + dc * 4) * 4u,
                         kg + (size_t)row * DD + dc * 4);
                }
            }
            CP_COMMIT();
            if (i < NKT && tid < BC)
                smem[LM_OFF / 4 + (i & 1) * BC + tid] = __log2f(mv) - FIXMAX;
            if (i + 1 < NKT && tid < BC) mv = (float)Mp[(size_t)(i + 1) * BC + tid];
            CP_WAIT(1);
            BAR(1);

            if (i < NKT) {
                const uint32_t* Ksu = (const uint32_t*)(smem + ((i & 1) ? KSTG_B / 4 : 0));
                #pragma unroll
                for (int n = 0; n < 8; n++) { sc[n][0]=0.f; sc[n][1]=0.f; sc[n][2]=0.f; sc[n][3]=0.f; }
                #pragma unroll
                for (int ks = 0; ks < 16; ks++) {
                    #pragma unroll
                    for (int n = 0; n < 8; n++) {
                        const uint32_t* kr = Ksu + (n * 8 + g) * PADF + ks * 8 + tq;
                        mma8(sc[n], qa[ks], kr[0], kr[4]);
                    }
                }
                const float* lmp = smem + LM_OFF / 4 + (i & 1) * BC;
                float ls0 = 0.f, ls1 = 0.f;
                #pragma unroll
                for (int n = 0; n < 8; n++) {
                    float lA = lmp[n * 8 + 2 * tq];
                    float lB = lmp[n * 8 + 2 * tq + 1];
                    sc[n][0] = ex2f(fmaf(sc[n][0], scale2, lA));
                    sc[n][1] = ex2f(fmaf(sc[n][1], scale2, lB));
                    sc[n][2] = ex2f(fmaf(sc[n][2], scale2, lA));
                    sc[n][3] = ex2f(fmaf(sc[n][3], scale2, lB));
                    ls0 += sc[n][0] + sc[n][1];
                    ls1 += sc[n][2] + sc[n][3];
                }
                l_r[0] += ls0; l_r[1] += ls1;
            }
            BAR(2);
            if (i < NKT) {                      // publish P(i): per-n chunk {c0,c2,c1,c3}
                #pragma unroll
                for (int n = 0; n < 8; n++) {
                    STS128(pbase + (uint32_t)n * 16u,
                           f2tf(sc[n][0]), f2tf(sc[n][2]), f2tf(sc[n][1]), f2tf(sc[n][3]));
                }
            }
        }

        // epilogue A: row normalizers
        float lt0 = l_r[0];
        lt0 += __shfl_xor_sync(0xffffffffu, lt0, 1);
        lt0 += __shfl_xor_sync(0xffffffffu, lt0, 2);
        float lt1 = l_r[1];
        lt1 += __shfl_xor_sync(0xffffffffu, lt1, 1);
        lt1 += __shfl_xor_sync(0xffffffffu, lt1, 2);
        if (tq == 0) {
            smem[LINV_OFF / 4 + wg * 16 + g]     = __fdividef(comp, lt0);
            smem[LINV_OFF / 4 + wg * 16 + g + 8] = __fdividef(comp, lt1);
        }
        BAR(3);
    } else {
        // ===================== GROUP B: PV accumulation =====================
        const int tidB = tid - 256;
        const int wg   = tidB >> 5;             // 0..7
        __syncthreads();                        // matches A's post-frag sync

        // V(0) into stage 0
        {
            const float* vg = Vp;
            #pragma unroll
            for (int i = 0; i < 8; i++) {
                int idx = tidB + i * 256;
                int row = idx >> 5, dc = idx & 31;
                cp16(sb + V_OFF + (uint32_t)(row * PADF + dc * 4) * 4u,
                     vg + (size_t)row * DD + dc * 4);
            }
        }
        CP_COMMIT();

        float o[16][4];
        #pragma unroll
        for (int n = 0; n < 16; n++) { o[n][0]=0.f; o[n][1]=0.f; o[n][2]=0.f; o[n][3]=0.f; }
        const uint32_t pbase = sb + P_OFF + (uint32_t)tidB * PCH;

        #pragma unroll 1
        for (int i = 0; i <= NKT; i++) {
            if (i + 1 < NKT) {                  // issue V(i+1)
                const uint32_t vd = sb + V_OFF + (uint32_t)((i + 1) % 3) * KSTG_B;
                const float* vg = Vp + (size_t)(i + 1) * BC * DD;
                #pragma unroll
                for (int j = 0; j < 8; j++) {
                    int idx = tidB + j * 256;
                    int row = idx >> 5, dc = idx & 31;
                    cp16(vd + (uint32_t)(row * PADF + dc * 4) * 4u,
                         vg + (size_t)row * DD + dc * 4);
                }
            }
            CP_COMMIT();
            CP_WAIT(2);
            BAR(1);

            if (i >= 1) {
                uint32_t pa[8][4];
                #pragma unroll
                for (int ks = 0; ks < 8; ks++)
                    LDS128(pa[ks][0], pa[ks][1], pa[ks][2], pa[ks][3],
                           pbase + (uint32_t)ks * 16u);
                const uint32_t* Vsu =
                    (const uint32_t*)(smem + V_OFF / 4 + ((i - 1) % 3) * (KSTG_B / 4));
                #pragma unroll
                for (int ks = 0; ks < 8; ks++) {
                    const uint32_t* vr0 = Vsu + (ks * 8 + 2 * tq) * PADF + g;
                    const uint32_t* vr1 = vr0 + PADF;
                    #pragma unroll
                    for (int n = 0; n < 16; n++)
                        mma8(o[n], pa[ks], vr0[n * 8], vr1[n * 8]);
                }
            }
            BAR(2);
        }

        BAR(3);
        const float inv0 = smem[LINV_OFF / 4 + wg * 16 + g];
        const float inv1 = smem[LINV_OFF / 4 + wg * 16 + g + 8];
        float* o0 = Op + (size_t)(wg * 16 + g) * DD;
        float* o1 = Op + (size_t)(wg * 16 + g + 8) * DD;
        #pragma unroll
        for (int n = 0; n < 16; n++) {
            int col = n * 8 + 2 * tq;
            float2 v0 = make_float2(o[n][0] * inv0, o[n][1] * inv0);
            float2 v1 = make_float2(o[n][2] * inv1, o[n][3] * inv1);
            *(float2*)(o0 + col) = v0;
            *(float2*)(o1 + col) = v1;
        }
    }
}

extern "C" void kernel_launch(void* const* d_in, const int* in_sizes, int n_in,
                              void* d_out, int out_size)
{
    const float* Q = (const float*)d_in[0];
    const float* K = (const float*)d_in[1];
    const float* V = (const float*)d_in[2];
    const int*   M = (const int*)d_in[3];
    float*       O = (float*)d_out;

    cudaFuncSetAttribute(ssa_ws_kernel,
                         cudaFuncAttributeMaxDynamicSharedMemorySize, SMEM_BYTES);
    dim3 grid(LQ / 128, BATCH * HEADS);
    ssa_ws_kernel<<<grid, NTHREADS, SMEM_BYTES>>>(Q, K, V, M, O);
}

// round 5
// speedup vs baseline: 1.1599x; 1.1599x over previous
#include <cuda_runtime.h>
#include <cstdint>
#include <math.h>

// SoftmaxSetAttention, GB300 (plain sm_103 target -> legacy mma.sync tf32).
// Crossbar-minimized warp specialization, M=32 rows per warp:
//   warps 0-3 (A): S = Q K^T (M=32,N=64), fixed-max base-2 softmax, P -> smem
//   warps 4-7 (B): O += P V  (M=32,N=128), P fragments via same-lane exchange
// Halves B-operand smem traffic vs 8-warp M=16 layout (the measured bottleneck).
// K: 2 stages (A-owned cp.async), V: 3 stages (B-owned), P: single buffer.
// Numerics: K/V raw fp32 bits into tf32 mma (RZ truncation) with bias
// compensation in scale (K) and epilogue (V); Q and P via cvt.rna.

#define BATCH 2
#define HEADS 16
#define LQ 2048
#define LK 2048
#define DD 128
#define BC 64
#define NKT 32
#define NTHREADS 256
#define PADF 132

#define KSTG_B   (BC * PADF * 4)            // 33792 bytes per K/V stage
#define K_OFF    0u                         // 2 stages (Q staging uses both: 67584 B)
#define V_OFF    (2u * KSTG_B)              // 3 stages
#define P_OFF    (V_OFF + 3u * KSTG_B)      // 128 chunks x 272 B
#define PCH      272u                       // 64 vals (256B) + 16B pad
#define LM_OFF   (P_OFF + 128u * PCH)       // float lm[2][64]
#define LINV_OFF (LM_OFF + 512u)            // float linv[128]
#define SMEM_BYTES (LINV_OFF + 512u)

__device__ __forceinline__ uint32_t f2tf(float x) {
    uint32_t r; asm("cvt.rna.tf32.f32 %0, %1;" : "=r"(r) : "f"(x)); return r;
}
__device__ __forceinline__ float ex2f(float x) {
    float r; asm("ex2.approx.ftz.f32 %0, %1;" : "=f"(r) : "f"(x)); return r;
}
__device__ __forceinline__ void mma8(float* c, const uint32_t* a, uint32_t b0, uint32_t b1) {
    asm volatile(
        "mma.sync.aligned.m16n8k8.row.col.f32.tf32.tf32.f32 "
        "{%0,%1,%2,%3}, {%4,%5,%6,%7}, {%8,%9}, {%0,%1,%2,%3};"
        : "+f"(c[0]), "+f"(c[1]), "+f"(c[2]), "+f"(c[3])
        : "r"(a[0]), "r"(a[1]), "r"(a[2]), "r"(a[3]), "r"(b0), "r"(b1));
}
__device__ __forceinline__ void cp16(uint32_t dst, const void* src) {
    asm volatile("cp.async.cg.shared.global [%0], [%1], 16;" :: "r"(dst), "l"(src));
}
#define CP_COMMIT() asm volatile("cp.async.commit_group;" ::: "memory")
#define CP_WAIT(n)  asm volatile("cp.async.wait_group %0;" :: "n"(n) : "memory")
#define BAR(id)     asm volatile("bar.sync %0, %1;" :: "r"(id), "r"(NTHREADS) : "memory")
#define STS128(a, v0, v1, v2, v3) \
    asm volatile("st.shared.v4.b32 [%0], {%1, %2, %3, %4};" \
                 :: "r"(a), "r"(v0), "r"(v1), "r"(v2), "r"(v3) : "memory")
#define LDS128(v0, v1, v2, v3, a) \
    asm volatile("ld.shared.v4.b32 {%0, %1, %2, %3}, [%4];" \
                 : "=r"(v0), "=r"(v1), "=r"(v2), "=r"(v3) : "r"(a))

__global__ void __launch_bounds__(NTHREADS, 1)
ssa_m32_kernel(const float* __restrict__ Q, const float* __restrict__ K,
               const float* __restrict__ V, const int* __restrict__ MULT,
               float* __restrict__ O)
{
    extern __shared__ float smem[];
    const uint32_t sb = (uint32_t)__cvta_generic_to_shared(smem);

    const int tid  = threadIdx.x;
    const int lane = tid & 31;
    const int g    = lane >> 2;
    const int tq   = lane & 3;
    const int bh   = blockIdx.y;
    const int qt   = blockIdx.x;
    const int b    = bh / HEADS;

    const float* Qp = Q + ((size_t)bh * LQ + (size_t)qt * 128) * DD;
    const float* Kp = K + (size_t)bh * LK * DD;
    const float* Vp = V + (size_t)bh * LK * DD;
    const int*   Mp = MULT + (size_t)b * LK;
    float*       Op = O + ((size_t)bh * LQ + (size_t)qt * 128) * DD;

    const float scale2 = (1.4426950408889634f / 11.313708498984760f) * (1.0f + 0.000244140625f);
    const float FIXMAX = 16.0f;
    const float comp   = 1.0f + 0.000244140625f;

    // ---- uniform prologue: stage Q (PAD-132 layout) into K region ----
    #pragma unroll
    for (int i = 0; i < 16; i++) {
        int idx = tid + i * NTHREADS;          // 0..4095 float4 chunks
        int row = idx >> 5, dc = idx & 31;
        cp16(sb + (uint32_t)(row * PADF + dc * 4) * 4u, Qp + (size_t)row * DD + dc * 4);
    }
    CP_COMMIT();
    CP_WAIT(0);
    __syncthreads();

    if (tid < 128) {
        // ============ GROUP A (4 warps, M=32): S + softmax + P publish ============
        const int wa = tid >> 5;               // 0..3
        uint32_t qa[16][8];                    // [ks][mt*4+j], rows wa*32+mt*16+g(+8)
        {
            #pragma unroll
            for (int mt = 0; mt < 2; mt++) {
                const int r0 = wa * 32 + mt * 16 + g;
                const float* q0 = smem + r0 * PADF;
                const float* q1 = smem + (r0 + 8) * PADF;
                #pragma unroll
                for (int ks = 0; ks < 16; ks++) {
                    qa[ks][mt * 4 + 0] = f2tf(q0[ks * 8 + tq]);
                    qa[ks][mt * 4 + 1] = f2tf(q1[ks * 8 + tq]);
                    qa[ks][mt * 4 + 2] = f2tf(q0[ks * 8 + tq + 4]);
                    qa[ks][mt * 4 + 3] = f2tf(q1[ks * 8 + tq + 4]);
                }
            }
        }
        __syncthreads();                        // Q consumed; K stages may be written

        float mv = 1.0f;
        if (tid < BC) mv = (float)Mp[tid];

        // K(0) into stage 0: 2048 chunks / 128 threads = 16 each
        {
            #pragma unroll
            for (int i = 0; i < 16; i++) {
                int idx = tid + i * 128;
                int row = idx >> 5, dc = idx & 31;
                cp16(sb + K_OFF + (uint32_t)(row * PADF + dc * 4) * 4u,
                     Kp + (size_t)row * DD + dc * 4);
            }
        }
        CP_COMMIT();

        float l_r[2][2] = {{0.f, 0.f}, {0.f, 0.f}};
        float sc[8][8];                         // [n][mt*4+j]
        const uint32_t pbase = sb + P_OFF + (uint32_t)tid * PCH;

        #pragma unroll 1
        for (int i = 0; i <= NKT; i++) {
            if (i + 1 < NKT) {                  // issue K(i+1)
                const uint32_t kd = sb + K_OFF + (uint32_t)((i + 1) & 1) * KSTG_B;
                const float* kg = Kp + (size_t)(i + 1) * BC * DD;
                #pragma unroll
                for (int j = 0; j < 16; j++) {
                    int idx = tid + j * 128;
                    int row = idx >> 5, dc = idx & 31;
                    cp16(kd + (uint32_t)(row * PADF + dc * 4) * 4u,
                         kg + (size_t)row * DD + dc * 4);
                }
            }
            CP_COMMIT();
            if (i < NKT && tid < BC)
                smem[LM_OFF / 4 + (i & 1) * BC + tid] = __log2f(mv) - FIXMAX;
            if (i + 1 < NKT && tid < BC) mv = (float)Mp[(size_t)(i + 1) * BC + tid];
            CP_WAIT(1);
            BAR(1);

            if (i < NKT) {
                const uint32_t* Ksu = (const uint32_t*)(smem + ((i & 1) ? KSTG_B / 4 : 0));
                #pragma unroll
                for (int n = 0; n < 8; n++)
                    #pragma unroll
                    for (int j = 0; j < 8; j++) sc[n][j] = 0.f;
                #pragma unroll
                for (int ks = 0; ks < 16; ks++) {
                    #pragma unroll
                    for (int n = 0; n < 8; n++) {
                        const uint32_t* kr = Ksu + (n * 8 + g) * PADF + ks * 8 + tq;
                        uint32_t b0 = kr[0], b1 = kr[4];
                        mma8(&sc[n][0], &qa[ks][0], b0, b1);
                        mma8(&sc[n][4], &qa[ks][4], b0, b1);
                    }
                }
                const float* lmp = smem + LM_OFF / 4 + (i & 1) * BC;
                #pragma unroll
                for (int n = 0; n < 8; n++) {
                    float lA = lmp[n * 8 + 2 * tq];
                    float lB = lmp[n * 8 + 2 * tq + 1];
                    #pragma unroll
                    for (int mt = 0; mt < 2; mt++) {
                        float p0 = ex2f(fmaf(sc[n][mt*4+0], scale2, lA));
                        float p1 = ex2f(fmaf(sc[n][mt*4+1], scale2, lB));
                        float p2 = ex2f(fmaf(sc[n][mt*4+2], scale2, lA));
                        float p3 = ex2f(fmaf(sc[n][mt*4+3], scale2, lB));
                        sc[n][mt*4+0] = p0; sc[n][mt*4+1] = p1;
                        sc[n][mt*4+2] = p2; sc[n][mt*4+3] = p3;
                        l_r[mt][0] += p0 + p1;
                        l_r[mt][1] += p2 + p3;
                    }
                }
            }
            BAR(2);
            if (i < NKT) {                      // publish P(i): chunk (mt*8+n), {c0,c2,c1,c3}
                #pragma unroll
                for (int mt = 0; mt < 2; mt++)
                    #pragma unroll
                    for (int n = 0; n < 8; n++)
                        STS128(pbase + (uint32_t)(mt * 8 + n) * 16u,
                               f2tf(sc[n][mt*4+0]), f2tf(sc[n][mt*4+2]),
                               f2tf(sc[n][mt*4+1]), f2tf(sc[n][mt*4+3]));
            }
        }

        // epilogue A: row normalizers
        #pragma unroll
        for (int mt = 0; mt < 2; mt++) {
            float lt0 = l_r[mt][0];
            lt0 += __shfl_xor_sync(0xffffffffu, lt0, 1);
            lt0 += __shfl_xor_sync(0xffffffffu, lt0, 2);
            float lt1 = l_r[mt][1];
            lt1 += __shfl_xor_sync(0xffffffffu, lt1, 1);
            lt1 += __shfl_xor_sync(0xffffffffu, lt1, 2);
            if (tq == 0) {
                smem[LINV_OFF / 4 + wa * 32 + mt * 16 + g]     = __fdividef(comp, lt0);
                smem[LINV_OFF / 4 + wa * 32 + mt * 16 + g + 8] = __fdividef(comp, lt1);
            }
        }
        BAR(3);
    } else {
        // ============ GROUP B (4 warps, M=32): O += P V ============
        const int tb = tid - 128;
        const int wb = tb >> 5;                 // 0..3
        __syncthreads();                        // matches A's post-frag sync

        // V(0) into stage 0
        {
            #pragma unroll
            for (int i = 0; i < 16; i++) {
                int idx = tb + i * 128;
                int row = idx >> 5, dc = idx & 31;
                cp16(sb + V_OFF + (uint32_t)(row * PADF + dc * 4) * 4u,
                     Vp + (size_t)row * DD + dc * 4);
            }
        }
        CP_COMMIT();

        float o[2][16][4];
        #pragma unroll
        for (int mt = 0; mt < 2; mt++)
            #pragma unroll
            for (int n = 0; n < 16; n++)
                { o[mt][n][0]=0.f; o[mt][n][1]=0.f; o[mt][n][2]=0.f; o[mt][n][3]=0.f; }
        const uint32_t pbase = sb + P_OFF + (uint32_t)tb * PCH;

        #pragma unroll 1
        for (int i = 0; i <= NKT; i++) {
            if (i + 1 < NKT) {                  // issue V(i+1)
                const uint32_t vd = sb + V_OFF + (uint32_t)((i + 1) % 3) * KSTG_B;
                const float* vg = Vp + (size_t)(i + 1) * BC * DD;
                #pragma unroll
                for (int j = 0; j < 16; j++) {
                    int idx = tb + j * 128;
                    int row = idx >> 5, dc = idx & 31;
                    cp16(vd + (uint32_t)(row * PADF + dc * 4) * 4u,
                         vg + (size_t)row * DD + dc * 4);
                }
            }
            CP_COMMIT();
            CP_WAIT(2);
            BAR(1);

            if (i >= 1) {
                uint32_t pa[2][8][4];           // [mt][ks][4]
                #pragma unroll
                for (int mt = 0; mt < 2; mt++)
                    #pragma unroll
                    for (int ks = 0; ks < 8; ks++)
                        LDS128(pa[mt][ks][0], pa[mt][ks][1], pa[mt][ks][2], pa[mt][ks][3],
                               pbase + (uint32_t)(mt * 8 + ks) * 16u);
                const uint32_t* Vsu =
                    (const uint32_t*)(smem + V_OFF / 4 + ((i - 1) % 3) * (KSTG_B / 4));
                #pragma unroll
                for (int ks = 0; ks < 8; ks++) {
                    const uint32_t* vr0 = Vsu + (ks * 8 + 2 * tq) * PADF + g;
                    const uint32_t* vr1 = vr0 + PADF;
                    #pragma unroll
                    for (int n = 0; n < 16; n++) {
                        uint32_t b0 = vr0[n * 8], b1 = vr1[n * 8];
                        mma8(o[0][n], pa[0][ks], b0, b1);
                        mma8(o[1][n], pa[1][ks], b0, b1);
                    }
                }
            }
            BAR(2);
        }

        BAR(3);
        #pragma unroll
        for (int mt = 0; mt < 2; mt++) {
            const float inv0 = smem[LINV_OFF / 4 + wb * 32 + mt * 16 + g];
            const float inv1 = smem[LINV_OFF / 4 + wb * 32 + mt * 16 + g + 8];
            float* o0 = Op + (size_t)(wb * 32 + mt * 16 + g) * DD;
            float* o1 = Op + (size_t)(wb * 32 + mt * 16 + g + 8) * DD;
            #pragma unroll
            for (int n = 0; n < 16; n++) {
                int col = n * 8 + 2 * tq;
                float2 v0 = make_float2(o[mt][n][0] * inv0, o[mt][n][1] * inv0);
                float2 v1 = make_float2(o[mt][n][2] * inv1, o[mt][n][3] * inv1);
                *(float2*)(o0 + col) = v0;
                *(float2*)(o1 + col) = v1;
            }
        }
    }
}

extern "C" void kernel_launch(void* const* d_in, const int* in_sizes, int n_in,
                              void* d_out, int out_size)
{
    const float* Q = (const float*)d_in[0];
    const float* K = (const float*)d_in[1];
    const float* V = (const float*)d_in[2];
    const int*   M = (const int*)d_in[3];
    float*       O = (float*)d_out;

    cudaFuncSetAttribute(ssa_m32_kernel,
                         cudaFuncAttributeMaxDynamicSharedMemorySize, SMEM_BYTES);
    dim3 grid(LQ / 128, BATCH * HEADS);
    ssa_m32_kernel<<<grid, NTHREADS, SMEM_BYTES>>>(Q, K, V, M, O);
}

// round 6
// speedup vs baseline: 1.2234x; 1.0547x over previous
#include <cuda_runtime.h>
#include <cstdint>
#include <math.h>

// SoftmaxSetAttention, GB300 (plain sm_103 target -> legacy mma.sync tf32).
// Warp specialization, M=32/warp, softmax moved to consumer group:
//   warps 0-3 (A): S = Q K^T (M=32,N=64), publish RAW scores to smem
//   warps 4-7 (B): bias+exp+l on loaded S fragments, O += P V, own epilogue
// Balances spans so the shared tensor pipe (512 HMMA x ~8cyc = 4096 cyc/tile
// per SMSP) is the limiter instead of A's serial softmax tail.
// Numerics identical to round 5: K/V raw fp32 bits into tf32 mma (RZ trunc)
// with bias compensation in scale (K) and epilogue (V); Q and P via cvt.rna.

#define BATCH 2
#define HEADS 16
#define LQ 2048
#define LK 2048
#define DD 128
#define BC 64
#define NKT 32
#define NTHREADS 256
#define PADF 132

#define KSTG_B   (BC * PADF * 4)            // 33792 bytes per K/V stage
#define K_OFF    0u                         // 2 stages (Q staging uses both)
#define V_OFF    (2u * KSTG_B)              // 3 stages
#define P_OFF    (V_OFF + 3u * KSTG_B)      // 128 chunks x 272 B (raw S exchange)
#define PCH      272u                       // 64 vals (256B) + 16B pad
#define LM_OFF   (P_OFF + 128u * PCH)       // float lm[2][64]
#define SMEM_BYTES (LM_OFF + 512u)

__device__ __forceinline__ uint32_t f2tf(float x) {
    uint32_t r; asm("cvt.rna.tf32.f32 %0, %1;" : "=r"(r) : "f"(x)); return r;
}
__device__ __forceinline__ float ex2f(float x) {
    float r; asm("ex2.approx.ftz.f32 %0, %1;" : "=f"(r) : "f"(x)); return r;
}
__device__ __forceinline__ void mma8(float* c, const uint32_t* a, uint32_t b0, uint32_t b1) {
    asm volatile(
        "mma.sync.aligned.m16n8k8.row.col.f32.tf32.tf32.f32 "
        "{%0,%1,%2,%3}, {%4,%5,%6,%7}, {%8,%9}, {%0,%1,%2,%3};"
        : "+f"(c[0]), "+f"(c[1]), "+f"(c[2]), "+f"(c[3])
        : "r"(a[0]), "r"(a[1]), "r"(a[2]), "r"(a[3]), "r"(b0), "r"(b1));
}
__device__ __forceinline__ void cp16(uint32_t dst, const void* src) {
    asm volatile("cp.async.cg.shared.global [%0], [%1], 16;" :: "r"(dst), "l"(src));
}
#define CP_COMMIT() asm volatile("cp.async.commit_group;" ::: "memory")
#define CP_WAIT(n)  asm volatile("cp.async.wait_group %0;" :: "n"(n) : "memory")
#define BAR(id)     asm volatile("bar.sync %0, %1;" :: "r"(id), "r"(NTHREADS) : "memory")
#define STS128(a, v0, v1, v2, v3) \
    asm volatile("st.shared.v4.b32 [%0], {%1, %2, %3, %4};" \
                 :: "r"(a), "r"(v0), "r"(v1), "r"(v2), "r"(v3) : "memory")
#define LDS128F(v0, v1, v2, v3, a) \
    asm volatile("ld.shared.v4.b32 {%0, %1, %2, %3}, [%4];" \
                 : "=f"(v0), "=f"(v1), "=f"(v2), "=f"(v3) : "r"(a))

__global__ void __launch_bounds__(NTHREADS, 1)
ssa_cs_kernel(const float* __restrict__ Q, const float* __restrict__ K,
              const float* __restrict__ V, const int* __restrict__ MULT,
              float* __restrict__ O)
{
    extern __shared__ float smem[];
    const uint32_t sb = (uint32_t)__cvta_generic_to_shared(smem);

    const int tid  = threadIdx.x;
    const int lane = tid & 31;
    const int g    = lane >> 2;
    const int tq   = lane & 3;
    const int bh   = blockIdx.y;
    const int qt   = blockIdx.x;
    const int b    = bh / HEADS;

    const float* Qp = Q + ((size_t)bh * LQ + (size_t)qt * 128) * DD;
    const float* Kp = K + (size_t)bh * LK * DD;
    const float* Vp = V + (size_t)bh * LK * DD;
    const int*   Mp = MULT + (size_t)b * LK;
    float*       Op = O + ((size_t)bh * LQ + (size_t)qt * 128) * DD;

    const float scale2 = (1.4426950408889634f / 11.313708498984760f) * (1.0f + 0.000244140625f);
    const float FIXMAX = 16.0f;
    const float comp   = 1.0f + 0.000244140625f;

    // ---- uniform prologue: stage Q (PAD-132 layout) into K region ----
    #pragma unroll
    for (int i = 0; i < 16; i++) {
        int idx = tid + i * NTHREADS;
        int row = idx >> 5, dc = idx & 31;
        cp16(sb + (uint32_t)(row * PADF + dc * 4) * 4u, Qp + (size_t)row * DD + dc * 4);
    }
    CP_COMMIT();
    CP_WAIT(0);
    __syncthreads();

    if (tid < 128) {
        // ============ GROUP A (4 warps, M=32): S = Q K^T, publish raw S ============
        const int wa = tid >> 5;
        uint32_t qa[16][8];
        {
            #pragma unroll
            for (int mt = 0; mt < 2; mt++) {
                const int r0 = wa * 32 + mt * 16 + g;
                const float* q0 = smem + r0 * PADF;
                const float* q1 = smem + (r0 + 8) * PADF;
                #pragma unroll
                for (int ks = 0; ks < 16; ks++) {
                    qa[ks][mt * 4 + 0] = f2tf(q0[ks * 8 + tq]);
                    qa[ks][mt * 4 + 1] = f2tf(q1[ks * 8 + tq]);
                    qa[ks][mt * 4 + 2] = f2tf(q0[ks * 8 + tq + 4]);
                    qa[ks][mt * 4 + 3] = f2tf(q1[ks * 8 + tq + 4]);
                }
            }
        }
        __syncthreads();                        // Q consumed; K stages may be written

        float mv = 1.0f;
        if (tid < BC) mv = (float)Mp[tid];

        // K(0) into stage 0
        #pragma unroll
        for (int i = 0; i < 16; i++) {
            int idx = tid + i * 128;
            int row = idx >> 5, dc = idx & 31;
            cp16(sb + K_OFF + (uint32_t)(row * PADF + dc * 4) * 4u,
                 Kp + (size_t)row * DD + dc * 4);
        }
        CP_COMMIT();

        float sc[8][8];
        const uint32_t pbase = sb + P_OFF + (uint32_t)tid * PCH;

        #pragma unroll 1
        for (int i = 0; i <= NKT; i++) {
            if (i + 1 < NKT) {                  // issue K(i+1)
                const uint32_t kd = sb + K_OFF + (uint32_t)((i + 1) & 1) * KSTG_B;
                const float* kg = Kp + (size_t)(i + 1) * BC * DD;
                #pragma unroll
                for (int j = 0; j < 16; j++) {
                    int idx = tid + j * 128;
                    int row = idx >> 5, dc = idx & 31;
                    cp16(kd + (uint32_t)(row * PADF + dc * 4) * 4u,
                         kg + (size_t)row * DD + dc * 4);
                }
            }
            CP_COMMIT();
            if (i < NKT && tid < BC)            // lm(i), consumed by B at iter i+1
                smem[LM_OFF / 4 + (i & 1) * BC + tid] = __log2f(mv) - FIXMAX;
            if (i + 1 < NKT && tid < BC) mv = (float)Mp[(size_t)(i + 1) * BC + tid];
            CP_WAIT(1);
            BAR(1);

            if (i < NKT) {
                const uint32_t* Ksu = (const uint32_t*)(smem + ((i & 1) ? KSTG_B / 4 : 0));
                #pragma unroll
                for (int n = 0; n < 8; n++)
                    #pragma unroll
                    for (int j = 0; j < 8; j++) sc[n][j] = 0.f;
                #pragma unroll
                for (int ks = 0; ks < 16; ks++) {
                    #pragma unroll
                    for (int n = 0; n < 8; n++) {
                        const uint32_t* kr = Ksu + (n * 8 + g) * PADF + ks * 8 + tq;
                        uint32_t b0 = kr[0], b1 = kr[4];
                        mma8(&sc[n][0], &qa[ks][0], b0, b1);
                        mma8(&sc[n][4], &qa[ks][4], b0, b1);
                    }
                }
            }
            BAR(2);
            if (i < NKT) {                      // publish RAW S(i): chunk (mt,n) = {c0,c2,c1,c3}
                #pragma unroll
                for (int mt = 0; mt < 2; mt++)
                    #pragma unroll
                    for (int n = 0; n < 8; n++)
                        STS128(pbase + (uint32_t)(mt * 8 + n) * 16u,
                               __float_as_uint(sc[n][mt*4+0]), __float_as_uint(sc[n][mt*4+2]),
                               __float_as_uint(sc[n][mt*4+1]), __float_as_uint(sc[n][mt*4+3]));
            }
        }
        // A epilogue: nothing (no more barriers on either path)
    } else {
        // ====== GROUP B (4 warps, M=32): softmax on S fragments + O += P V ======
        const int tb = tid - 128;
        const int wb = tb >> 5;
        __syncthreads();                        // matches A's post-frag sync

        // V(0) into stage 0
        #pragma unroll
        for (int i = 0; i < 16; i++) {
            int idx = tb + i * 128;
            int row = idx >> 5, dc = idx & 31;
            cp16(sb + V_OFF + (uint32_t)(row * PADF + dc * 4) * 4u,
                 Vp + (size_t)row * DD + dc * 4);
        }
        CP_COMMIT();

        float o[2][16][4];
        #pragma unroll
        for (int mt = 0; mt < 2; mt++)
            #pragma unroll
            for (int n = 0; n < 16; n++)
                { o[mt][n][0]=0.f; o[mt][n][1]=0.f; o[mt][n][2]=0.f; o[mt][n][3]=0.f; }
        float l_r[2][2] = {{0.f, 0.f}, {0.f, 0.f}};
        const uint32_t pbase = sb + P_OFF + (uint32_t)tb * PCH;

        #pragma unroll 1
        for (int i = 0; i <= NKT; i++) {
            if (i + 1 < NKT) {                  // issue V(i+1)
                const uint32_t vd = sb + V_OFF + (uint32_t)((i + 1) % 3) * KSTG_B;
                const float* vg = Vp + (size_t)(i + 1) * BC * DD;
                #pragma unroll
                for (int j = 0; j < 16; j++) {
                    int idx = tb + j * 128;
                    int row = idx >> 5, dc = idx & 31;
                    cp16(vd + (uint32_t)(row * PADF + dc * 4) * 4u,
                         vg + (size_t)row * DD + dc * 4);
                }
            }
            CP_COMMIT();
            CP_WAIT(2);
            BAR(1);

            if (i >= 1) {
                const float* lmp = smem + LM_OFF / 4 + ((i - 1) & 1) * BC;
                uint32_t pa[2][8][4];
                #pragma unroll
                for (int mt = 0; mt < 2; mt++) {
                    #pragma unroll
                    for (int ks = 0; ks < 8; ks++) {
                        float v0, v1, v2, v3;   // {rowR keyA, rowR+8 keyA, rowR keyB, rowR+8 keyB}
                        LDS128F(v0, v1, v2, v3, pbase + (uint32_t)(mt * 8 + ks) * 16u);
                        const float lA = lmp[ks * 8 + 2 * tq];
                        const float lB = lmp[ks * 8 + 2 * tq + 1];
                        float p0 = ex2f(fmaf(v0, scale2, lA));
                        float p1 = ex2f(fmaf(v1, scale2, lA));
                        float p2 = ex2f(fmaf(v2, scale2, lB));
                        float p3 = ex2f(fmaf(v3, scale2, lB));
                        l_r[mt][0] += p0 + p2;  // row R
                        l_r[mt][1] += p1 + p3;  // row R+8
                        pa[mt][ks][0] = f2tf(p0);
                        pa[mt][ks][1] = f2tf(p1);
                        pa[mt][ks][2] = f2tf(p2);
                        pa[mt][ks][3] = f2tf(p3);
                    }
                }
                const uint32_t* Vsu =
                    (const uint32_t*)(smem + V_OFF / 4 + ((i - 1) % 3) * (KSTG_B / 4));
                #pragma unroll
                for (int ks = 0; ks < 8; ks++) {
                    const uint32_t* vr0 = Vsu + (ks * 8 + 2 * tq) * PADF + g;
                    const uint32_t* vr1 = vr0 + PADF;
                    #pragma unroll
                    for (int n = 0; n < 16; n++) {
                        uint32_t b0 = vr0[n * 8], b1 = vr1[n * 8];
                        mma8(o[0][n], pa[0][ks], b0, b1);
                        mma8(o[1][n], pa[1][ks], b0, b1);
                    }
                }
            }
            BAR(2);
        }

        // B epilogue: finish l reduction (keys spread over tq lanes), normalize, store
        #pragma unroll
        for (int mt = 0; mt < 2; mt++) {
            float lt0 = l_r[mt][0];
            lt0 += __shfl_xor_sync(0xffffffffu, lt0, 1);
            lt0 += __shfl_xor_sync(0xffffffffu, lt0, 2);
            float lt1 = l_r[mt][1];
            lt1 += __shfl_xor_sync(0xffffffffu, lt1, 1);
            lt1 += __shfl_xor_sync(0xffffffffu, lt1, 2);
            const float inv0 = __fdividef(comp, lt0);
            const float inv1 = __fdividef(comp, lt1);
            float* o0 = Op + (size_t)(wb * 32 + mt * 16 + g) * DD;
            float* o1 = Op + (size_t)(wb * 32 + mt * 16 + g + 8) * DD;
            #pragma unroll
            for (int n = 0; n < 16; n++) {
                int col = n * 8 + 2 * tq;
                float2 v0 = make_float2(o[mt][n][0] * inv0, o[mt][n][1] * inv0);
                float2 v1 = make_float2(o[mt][n][2] * inv1, o[mt][n][3] * inv1);
                *(float2*)(o0 + col) = v0;
                *(float2*)(o1 + col) = v1;
            }
        }
    }
}

extern "C" void kernel_launch(void* const* d_in, const int* in_sizes, int n_in,
                              void* d_out, int out_size)
{
    const float* Q = (const float*)d_in[0];
    const float* K = (const float*)d_in[1];
    const float* V = (const float*)d_in[2];
    const int*   M = (const int*)d_in[3];
    float*       O = (float*)d_out;

    cudaFuncSetAttribute(ssa_cs_kernel,
                         cudaFuncAttributeMaxDynamicSharedMemorySize, SMEM_BYTES);
    dim3 grid(LQ / 128, BATCH * HEADS);
    ssa_cs_kernel<<<grid, NTHREADS, SMEM_BYTES>>>(Q, K, V, M, O);
}